// round 1
// baseline (speedup 1.0000x reference)
#include <cuda_runtime.h>

#define NN 100000
#define EE 1600000
#define GG 128

// ---------------- scratch (static device globals; no allocation) ----------------
__device__ __align__(16) float g_dinv[NN];            // deg -> dinv in place
__device__ __align__(16) float g_norm[EE];            // per-edge symmetric norm
__device__ __align__(16) float g_bufA[(size_t)NN * 64]; // h (gemm output)
__device__ __align__(16) float g_bufB[(size_t)NN * 64]; // aggregation accumulator
__device__ __align__(16) float g_pooled[GG * 64];
__device__ __align__(16) float g_bnsc[3][64];
__device__ __align__(16) float g_bnsh[3][64];

struct BNParams { const float* p[12]; };  // (gamma,beta,mean,var) x 3 layers

// ---------------- prep: deg init, pooled zero, BN scale/shift ----------------
__global__ void k_prep(BNParams bp) {
    int i = blockIdx.x * blockDim.x + threadIdx.x;
    if (i < NN) g_dinv[i] = 1.0f;                 // self-loop weight
    if (i < GG * 64) g_pooled[i] = 0.0f;
    if (i < 3 * 64) {
        int l = i >> 6, f = i & 63;
        const float* ga = bp.p[l * 4 + 0];
        const float* be = bp.p[l * 4 + 1];
        const float* mn = bp.p[l * 4 + 2];
        const float* va = bp.p[l * 4 + 3];
        float sc = ga[f] * rsqrtf(va[f] + 1e-5f);
        g_bnsc[l][f] = sc;
        g_bnsh[l][f] = be[f] - mn[f] * sc;
    }
}

__global__ void k_degacc(const int* __restrict__ col, const float* __restrict__ w) {
    int e = blockIdx.x * blockDim.x + threadIdx.x;
    if (e < EE) atomicAdd(&g_dinv[col[e]], w[e]);
}

__global__ void k_dinv() {
    int i = blockIdx.x * blockDim.x + threadIdx.x;
    if (i < NN) g_dinv[i] = rsqrtf(g_dinv[i]);    // deg >= 1 always
}

__global__ void k_norm(const int* __restrict__ row, const int* __restrict__ col,
                       const float* __restrict__ w) {
    int e = blockIdx.x * blockDim.x + threadIdx.x;
    if (e < EE) g_norm[e] = g_dinv[row[e]] * w[e] * g_dinv[col[e]];
}

// ---------------- fused GEMM: out = act(in) @ W ; epilogue writes h and self-loop init ----------------
// ACT: 0 = identity, 1 = relu then BN(layer l)
template <int ACT>
__device__ __forceinline__ void gemm_body(const float* __restrict__ in,
                                          const float* __restrict__ W,
                                          const float* __restrict__ bias, int l) {
    __shared__ float sW[64 * 64];
    __shared__ float sIn[32][65];
    int t = threadIdx.x;  // 256 threads

    const float4* W4 = (const float4*)W;
    float4* sW4 = (float4*)sW;
#pragma unroll
    for (int i = 0; i < 4; i++) sW4[t + 256 * i] = W4[t + 256 * i];

    int r0 = blockIdx.x * 32;  // NN divisible by 32 -> no bounds checks
#pragma unroll
    for (int i = 0; i < 2; i++) {
        int idx = t + 256 * i;       // 0..511 float4s in 32x64 tile
        int rr = idx >> 4;
        int cc = (idx & 15) * 4;
        float4 v = *(const float4*)(in + (size_t)(r0 + rr) * 64 + cc);
        if (ACT == 1) {
            v.x = fmaxf(v.x, 0.f) * g_bnsc[l][cc + 0] + g_bnsh[l][cc + 0];
            v.y = fmaxf(v.y, 0.f) * g_bnsc[l][cc + 1] + g_bnsh[l][cc + 1];
            v.z = fmaxf(v.z, 0.f) * g_bnsc[l][cc + 2] + g_bnsh[l][cc + 2];
            v.w = fmaxf(v.w, 0.f) * g_bnsc[l][cc + 3] + g_bnsh[l][cc + 3];
        }
        sIn[rr][cc + 0] = v.x; sIn[rr][cc + 1] = v.y;
        sIn[rr][cc + 2] = v.z; sIn[rr][cc + 3] = v.w;
    }
    __syncthreads();

    int rowi = t >> 3;
    int c0 = (t & 7) * 4;        // lanes cover cols [c0, c0+3] and [c0+32, c0+35]
    float4 a0 = make_float4(0.f, 0.f, 0.f, 0.f);
    float4 a1 = make_float4(0.f, 0.f, 0.f, 0.f);
#pragma unroll
    for (int k = 0; k < 64; k++) {
        float a = sIn[rowi][k];
        float4 w0 = *(const float4*)&sW[k * 64 + c0];
        float4 w1 = *(const float4*)&sW[k * 64 + c0 + 32];
        a0.x += a * w0.x; a0.y += a * w0.y; a0.z += a * w0.z; a0.w += a * w0.w;
        a1.x += a * w1.x; a1.y += a * w1.y; a1.z += a * w1.z; a1.w += a * w1.w;
    }

    int gr = r0 + rowi;
    float dv = g_dinv[gr];
    float snv = dv * dv;                      // self-loop norm dinv^2
    float4 b0 = *(const float4*)(bias + c0);
    float4 b1 = *(const float4*)(bias + c0 + 32);
    size_t base = (size_t)gr * 64;
    *(float4*)&g_bufA[base + c0]      = a0;
    *(float4*)&g_bufA[base + c0 + 32] = a1;
    float4 i0 = make_float4(a0.x * snv + b0.x, a0.y * snv + b0.y,
                            a0.z * snv + b0.z, a0.w * snv + b0.w);
    float4 i1 = make_float4(a1.x * snv + b1.x, a1.y * snv + b1.y,
                            a1.z * snv + b1.z, a1.w * snv + b1.w);
    *(float4*)&g_bufB[base + c0]      = i0;
    *(float4*)&g_bufB[base + c0 + 32] = i1;
}

__global__ void __launch_bounds__(256) k_gemm1(const float* __restrict__ x,
                                               const float* __restrict__ W,
                                               const float* __restrict__ b) {
    gemm_body<0>(x, W, b, 0);
}
__global__ void __launch_bounds__(256) k_gemm23(const float* __restrict__ W,
                                                const float* __restrict__ b, int l) {
    gemm_body<1>(g_bufB, W, b, l);
}

// ---------------- edge aggregation: bufB[col] += bufA[row] * norm ----------------
// 16 lanes per edge; each lane one float4; vector reduction to L2.
__global__ void __launch_bounds__(256) k_edge(const int* __restrict__ row,
                                              const int* __restrict__ col) {
    long long t = (long long)blockIdx.x * 256 + threadIdx.x;
    int e = (int)(t >> 4);
    if (e >= EE) return;
    int q = (int)(t & 15);
    int r = __ldg(row + e);
    int c = __ldg(col + e);
    float nv = __ldg(&g_norm[e]);
    float4 v = __ldg((const float4*)(g_bufA + (size_t)r * 64) + q);
    float* p = g_bufB + (size_t)c * 64 + (size_t)q * 4;
    asm volatile("red.global.add.v4.f32 [%0], {%1,%2,%3,%4};"
                 :: "l"(p), "f"(v.x * nv), "f"(v.y * nv), "f"(v.z * nv), "f"(v.w * nv)
                 : "memory");
}

// ---------------- BN3 + global_add_pool (batch is sorted: run-accumulate) ----------------
#define POOL_CHUNK 128
__global__ void k_pool(const int* __restrict__ batch) {
    int f = threadIdx.x;  // 64 threads: one per feature
    int start = blockIdx.x * POOL_CHUNK;
    int end = start + POOL_CHUNK;
    if (end > NN) end = NN;
    if (start >= NN) return;
    float sc = g_bnsc[2][f], sh = g_bnsh[2][f];
    int cur = batch[start];
    float acc = 0.f;
    for (int n = start; n < end; n++) {
        int b = batch[n];
        if (b != cur) {
            atomicAdd(&g_pooled[cur * 64 + f], acc);
            acc = 0.f;
            cur = b;
        }
        acc += g_bufB[(size_t)n * 64 + f] * sc + sh;
    }
    atomicAdd(&g_pooled[cur * 64 + f], acc);
}

// ---------------- FC: out[g] = relu(pooled[g]) . Wfc + bfc ----------------
__global__ void k_fc(const float* __restrict__ Wfc, const float* __restrict__ bfc,
                     float* __restrict__ out) {
    int g = threadIdx.x;  // 128
    float acc = 0.f;
#pragma unroll
    for (int k = 0; k < 64; k++)
        acc += fmaxf(g_pooled[g * 64 + k], 0.f) * Wfc[k];
    out[g] = acc + bfc[0];
}

// ---------------- launch ----------------
extern "C" void kernel_launch(void* const* d_in, const int* in_sizes, int n_in,
                              void* d_out, int out_size) {
    const float* x     = (const float*)d_in[0];
    const int*   ei    = (const int*)d_in[1];
    const int*   row   = ei;
    const int*   col   = ei + EE;
    const float* ew    = (const float*)d_in[2];
    const int*   batch = (const int*)d_in[3];
    const float* W1 = (const float*)d_in[4];
    const float* b1 = (const float*)d_in[5];
    const float* W2 = (const float*)d_in[6];
    const float* b2 = (const float*)d_in[7];
    const float* W3 = (const float*)d_in[8];
    const float* b3 = (const float*)d_in[9];
    const float* Wfc = (const float*)d_in[10];
    const float* bfc = (const float*)d_in[11];

    BNParams bp;
    for (int i = 0; i < 12; i++) bp.p[i] = (const float*)d_in[12 + i];

    int nb_n = (NN + 255) / 256;          // 391
    int nb_e = (EE + 255) / 256;          // 6250
    int nb_gemm = NN / 32;                // 3125
    long long edge_threads = (long long)EE * 16;
    int nb_edge = (int)((edge_threads + 255) / 256);  // 100000
    int nb_pool = (NN + POOL_CHUNK - 1) / POOL_CHUNK; // 782

    k_prep<<<nb_n, 256>>>(bp);
    k_degacc<<<nb_e, 256>>>(col, ew);
    k_dinv<<<nb_n, 256>>>();
    k_norm<<<nb_e, 256>>>(row, col, ew);

    // layer 1
    k_gemm1<<<nb_gemm, 256>>>(x, W1, b1);
    k_edge<<<nb_edge, 256>>>(row, col);
    // layer 2 (relu + bn1 fused into gemm input)
    k_gemm23<<<nb_gemm, 256>>>(W2, b2, 0);
    k_edge<<<nb_edge, 256>>>(row, col);
    // layer 3 (relu + bn2 fused into gemm input)
    k_gemm23<<<nb_gemm, 256>>>(W3, b3, 1);
    k_edge<<<nb_edge, 256>>>(row, col);

    // bn3 (no relu) + pool, then fc
    k_pool<<<nb_pool, 64>>>(batch);
    k_fc<<<1, 128>>>(Wfc, bfc, (float*)d_out);
}

// round 2
// speedup vs baseline: 1.3400x; 1.3400x over previous
#include <cuda_runtime.h>

#define NN 100000
#define EE 1600000
#define GG 128
#define SCAN_B 1024
#define SCAN_NBLK ((NN + SCAN_B - 1) / SCAN_B)   // 98

// ---------------- scratch (static device globals; no allocation) ----------------
__device__ __align__(16) float g_dinv[NN];              // weighted deg -> dinv in place
__device__ __align__(16) int   g_counts[NN];
__device__ __align__(16) int   g_offs[NN + 1];
__device__ __align__(16) int   g_cursor[NN];
__device__ __align__(16) int   g_bsum[SCAN_NBLK + 1];
__device__ __align__(16) int2  g_payload[EE];           // {src, norm-as-bits} sorted by dest
__device__ __align__(16) float g_bufA[(size_t)NN * 64]; // h (gemm output)
__device__ __align__(16) float g_bufB[(size_t)NN * 64]; // self-loop init / agg result
__device__ __align__(16) float g_pooled[GG * 64];
__device__ __align__(16) float g_bnsc[3][64];
__device__ __align__(16) float g_bnsh[3][64];

struct BNParams { const float* p[12]; };  // (gamma,beta,mean,var) x 3 layers

// ---------------- prep: deg init, counts zero, pooled zero, BN scale/shift ----------------
__global__ void k_prep(BNParams bp) {
    int i = blockIdx.x * blockDim.x + threadIdx.x;
    if (i < NN) { g_dinv[i] = 1.0f; g_counts[i] = 0; }   // self-loop weight
    if (i < GG * 64) g_pooled[i] = 0.0f;
    if (i < 3 * 64) {
        int l = i >> 6, f = i & 63;
        const float* ga = bp.p[l * 4 + 0];
        const float* be = bp.p[l * 4 + 1];
        const float* mn = bp.p[l * 4 + 2];
        const float* va = bp.p[l * 4 + 3];
        float sc = ga[f] * rsqrtf(va[f] + 1e-5f);
        g_bnsc[l][f] = sc;
        g_bnsh[l][f] = be[f] - mn[f] * sc;
    }
}

// per-edge: weighted degree + incoming-count histogram
__global__ void k_degcount(const int* __restrict__ col, const float* __restrict__ w) {
    int e = blockIdx.x * blockDim.x + threadIdx.x;
    if (e >= EE) return;
    int c = col[e];
    atomicAdd(&g_dinv[c], w[e]);
    atomicAdd(&g_counts[c], 1);
}

// ---------------- 3-phase exclusive scan of counts -> offs ----------------
__global__ void k_scan1() {
    __shared__ int s[SCAN_B];
    int t = threadIdx.x;
    int i = blockIdx.x * SCAN_B + t;
    int val = (i < NN) ? g_counts[i] : 0;
    s[t] = val;
    __syncthreads();
#pragma unroll
    for (int off = 1; off < SCAN_B; off <<= 1) {
        int a = (t >= off) ? s[t - off] : 0;
        __syncthreads();
        s[t] += a;
        __syncthreads();
    }
    if (i < NN) g_offs[i] = s[t] - val;          // exclusive
    if (t == SCAN_B - 1) g_bsum[blockIdx.x] = s[t];
}

__global__ void k_scan2() {
    if (threadIdx.x == 0) {
        int run = 0;
        for (int b = 0; b < SCAN_NBLK; b++) {
            int v = g_bsum[b];
            g_bsum[b] = run;
            run += v;
        }
    }
}

// add block offsets, init cursor, finalize dinv, set sentinel
__global__ void k_fix() {
    int i = blockIdx.x * blockDim.x + threadIdx.x;
    if (i < NN) {
        int o = g_offs[i] + g_bsum[i >> 10];
        g_offs[i] = o;
        g_cursor[i] = o;
        g_dinv[i] = rsqrtf(g_dinv[i]);
    }
    if (i == 0) g_offs[NN] = EE;
}

// scatter edges into dest-sorted order with fused norm
__global__ void k_scatter(const int* __restrict__ row, const int* __restrict__ col,
                          const float* __restrict__ w) {
    int e = blockIdx.x * blockDim.x + threadIdx.x;
    if (e >= EE) return;
    int r = row[e];
    int c = col[e];
    float nv = g_dinv[r] * w[e] * g_dinv[c];
    int pos = atomicAdd(&g_cursor[c], 1);
    g_payload[pos] = make_int2(r, __float_as_int(nv));
}

// ---------------- fused GEMM: out = act(in) @ W ; epilogue writes h and self-loop init ----------------
template <int ACT>
__device__ __forceinline__ void gemm_body(const float* __restrict__ in,
                                          const float* __restrict__ W,
                                          const float* __restrict__ bias, int l) {
    __shared__ float sW[64 * 64];
    __shared__ float sIn[32][65];
    int t = threadIdx.x;  // 256 threads

    const float4* W4 = (const float4*)W;
    float4* sW4 = (float4*)sW;
#pragma unroll
    for (int i = 0; i < 4; i++) sW4[t + 256 * i] = W4[t + 256 * i];

    int r0 = blockIdx.x * 32;  // NN divisible by 32 -> no bounds checks
#pragma unroll
    for (int i = 0; i < 2; i++) {
        int idx = t + 256 * i;       // 0..511 float4s in 32x64 tile
        int rr = idx >> 4;
        int cc = (idx & 15) * 4;
        float4 v = *(const float4*)(in + (size_t)(r0 + rr) * 64 + cc);
        if (ACT == 1) {
            v.x = fmaxf(v.x, 0.f) * g_bnsc[l][cc + 0] + g_bnsh[l][cc + 0];
            v.y = fmaxf(v.y, 0.f) * g_bnsc[l][cc + 1] + g_bnsh[l][cc + 1];
            v.z = fmaxf(v.z, 0.f) * g_bnsc[l][cc + 2] + g_bnsh[l][cc + 2];
            v.w = fmaxf(v.w, 0.f) * g_bnsc[l][cc + 3] + g_bnsh[l][cc + 3];
        }
        sIn[rr][cc + 0] = v.x; sIn[rr][cc + 1] = v.y;
        sIn[rr][cc + 2] = v.z; sIn[rr][cc + 3] = v.w;
    }
    __syncthreads();

    int rowi = t >> 3;
    int c0 = (t & 7) * 4;        // lanes cover cols [c0, c0+3] and [c0+32, c0+35]
    float4 a0 = make_float4(0.f, 0.f, 0.f, 0.f);
    float4 a1 = make_float4(0.f, 0.f, 0.f, 0.f);
#pragma unroll
    for (int k = 0; k < 64; k++) {
        float a = sIn[rowi][k];
        float4 w0 = *(const float4*)&sW[k * 64 + c0];
        float4 w1 = *(const float4*)&sW[k * 64 + c0 + 32];
        a0.x += a * w0.x; a0.y += a * w0.y; a0.z += a * w0.z; a0.w += a * w0.w;
        a1.x += a * w1.x; a1.y += a * w1.y; a1.z += a * w1.z; a1.w += a * w1.w;
    }

    int gr = r0 + rowi;
    float dv = g_dinv[gr];
    float snv = dv * dv;                      // self-loop norm dinv^2
    float4 b0 = *(const float4*)(bias + c0);
    float4 b1 = *(const float4*)(bias + c0 + 32);
    size_t base = (size_t)gr * 64;
    *(float4*)&g_bufA[base + c0]      = a0;
    *(float4*)&g_bufA[base + c0 + 32] = a1;
    float4 i0 = make_float4(a0.x * snv + b0.x, a0.y * snv + b0.y,
                            a0.z * snv + b0.z, a0.w * snv + b0.w);
    float4 i1 = make_float4(a1.x * snv + b1.x, a1.y * snv + b1.y,
                            a1.z * snv + b1.z, a1.w * snv + b1.w);
    *(float4*)&g_bufB[base + c0]      = i0;
    *(float4*)&g_bufB[base + c0 + 32] = i1;
}

__global__ void __launch_bounds__(256) k_gemm1(const float* __restrict__ x,
                                               const float* __restrict__ W,
                                               const float* __restrict__ b) {
    gemm_body<0>(x, W, b, 0);
}
__global__ void __launch_bounds__(256) k_gemm23(const float* __restrict__ W,
                                                const float* __restrict__ b, int l) {
    gemm_body<1>(g_bufB, W, b, l);
}

// ---------------- CSR aggregation: bufB[c] = selfinit[c] + sum_e norm_e * bufA[src_e] ----------------
// half-warp (16 lanes) per destination; lane q owns float4 #q of the 64-feature row.
__global__ void __launch_bounds__(256) k_agg() {
    int t = threadIdx.x;
    int q = t & 15;
    int c = blockIdx.x * 16 + (t >> 4);      // NN % 16 == 0 -> no bounds check
    int e = g_offs[c];
    int end = g_offs[c + 1];

    const float4* __restrict__ A4 = (const float4*)g_bufA;
    float4* B4 = (float4*)g_bufB;

    float4 acc = B4[(size_t)c * 16 + q];     // self-loop + bias init

    // unroll-by-2 for MLP on the payload->gather chain
    for (; e + 1 < end; e += 2) {
        int2 p0 = __ldg(&g_payload[e]);
        int2 p1 = __ldg(&g_payload[e + 1]);
        float4 v0 = __ldg(&A4[(size_t)p0.x * 16 + q]);
        float4 v1 = __ldg(&A4[(size_t)p1.x * 16 + q]);
        float n0 = __int_as_float(p0.y);
        float n1 = __int_as_float(p1.y);
        acc.x += v0.x * n0; acc.y += v0.y * n0; acc.z += v0.z * n0; acc.w += v0.w * n0;
        acc.x += v1.x * n1; acc.y += v1.y * n1; acc.z += v1.z * n1; acc.w += v1.w * n1;
    }
    if (e < end) {
        int2 p0 = __ldg(&g_payload[e]);
        float4 v0 = __ldg(&A4[(size_t)p0.x * 16 + q]);
        float n0 = __int_as_float(p0.y);
        acc.x += v0.x * n0; acc.y += v0.y * n0; acc.z += v0.z * n0; acc.w += v0.w * n0;
    }
    B4[(size_t)c * 16 + q] = acc;
}

// ---------------- BN3 + global_add_pool (batch is sorted: run-accumulate) ----------------
#define POOL_CHUNK 128
__global__ void k_pool(const int* __restrict__ batch) {
    int f = threadIdx.x;  // 64 threads: one per feature
    int start = blockIdx.x * POOL_CHUNK;
    int end = start + POOL_CHUNK;
    if (end > NN) end = NN;
    if (start >= NN) return;
    float sc = g_bnsc[2][f], sh = g_bnsh[2][f];
    int cur = batch[start];
    float acc = 0.f;
    for (int n = start; n < end; n++) {
        int b = batch[n];
        if (b != cur) {
            atomicAdd(&g_pooled[cur * 64 + f], acc);
            acc = 0.f;
            cur = b;
        }
        acc += g_bufB[(size_t)n * 64 + f] * sc + sh;
    }
    atomicAdd(&g_pooled[cur * 64 + f], acc);
}

// ---------------- FC: out[g] = relu(pooled[g]) . Wfc + bfc ----------------
__global__ void k_fc(const float* __restrict__ Wfc, const float* __restrict__ bfc,
                     float* __restrict__ out) {
    int g = threadIdx.x;  // 128
    float acc = 0.f;
#pragma unroll
    for (int k = 0; k < 64; k++)
        acc += fmaxf(g_pooled[g * 64 + k], 0.f) * Wfc[k];
    out[g] = acc + bfc[0];
}

// ---------------- launch ----------------
extern "C" void kernel_launch(void* const* d_in, const int* in_sizes, int n_in,
                              void* d_out, int out_size) {
    const float* x     = (const float*)d_in[0];
    const int*   ei    = (const int*)d_in[1];
    const int*   row   = ei;
    const int*   col   = ei + EE;
    const float* ew    = (const float*)d_in[2];
    const int*   batch = (const int*)d_in[3];
    const float* W1 = (const float*)d_in[4];
    const float* b1 = (const float*)d_in[5];
    const float* W2 = (const float*)d_in[6];
    const float* b2 = (const float*)d_in[7];
    const float* W3 = (const float*)d_in[8];
    const float* b3 = (const float*)d_in[9];
    const float* Wfc = (const float*)d_in[10];
    const float* bfc = (const float*)d_in[11];

    BNParams bp;
    for (int i = 0; i < 12; i++) bp.p[i] = (const float*)d_in[12 + i];

    int nb_n = (NN + 255) / 256;          // 391
    int nb_e = (EE + 255) / 256;          // 6250
    int nb_gemm = NN / 32;                // 3125
    int nb_agg = NN / 16;                 // 6250
    int nb_pool = (NN + POOL_CHUNK - 1) / POOL_CHUNK; // 782

    // CSR build + norm precompute
    k_prep<<<nb_n, 256>>>(bp);
    k_degcount<<<nb_e, 256>>>(col, ew);
    k_scan1<<<SCAN_NBLK, SCAN_B>>>();
    k_scan2<<<1, 32>>>();
    k_fix<<<nb_n, 256>>>();
    k_scatter<<<nb_e, 256>>>(row, col, ew);

    // layer 1
    k_gemm1<<<nb_gemm, 256>>>(x, W1, b1);
    k_agg<<<nb_agg, 256>>>();
    // layer 2 (relu + bn1 fused into gemm input)
    k_gemm23<<<nb_gemm, 256>>>(W2, b2, 0);
    k_agg<<<nb_agg, 256>>>();
    // layer 3 (relu + bn2 fused into gemm input)
    k_gemm23<<<nb_gemm, 256>>>(W3, b3, 1);
    k_agg<<<nb_agg, 256>>>();

    // bn3 (no relu) + pool, then fc
    k_pool<<<nb_pool, 64>>>(batch);
    k_fc<<<1, 128>>>(Wfc, bfc, (float*)d_out);
}

// round 3
// speedup vs baseline: 1.3820x; 1.0314x over previous
#include <cuda_runtime.h>
#include <cuda_fp16.h>

#define NN 100000
#define EE 1600000
#define GG 128
#define SCAN_B 1024
#define SCAN_NBLK ((NN + SCAN_B - 1) / SCAN_B)   // 98

// ---------------- scratch (static device globals; no allocation) ----------------
__device__ __align__(16) float g_dinv[NN];              // weighted deg -> dinv in place
__device__ __align__(16) int   g_counts[NN];
__device__ __align__(16) int   g_offs[NN + 1];
__device__ __align__(16) int   g_cursor[NN];
__device__ __align__(16) int   g_bsum[SCAN_NBLK + 1];
__device__ __align__(16) int2  g_payload[EE];           // {src, norm-as-bits} sorted by dest
__device__ __align__(16) __half g_bufA[(size_t)NN * 64]; // h (gemm output, fp16)
__device__ __align__(16) float g_bufB[(size_t)NN * 64]; // self-loop init / agg result (fp32)
__device__ __align__(16) float g_pooled[GG * 64];
__device__ __align__(16) float g_bnsc[3][64];
__device__ __align__(16) float g_bnsh[3][64];

struct BNParams { const float* p[12]; };  // (gamma,beta,mean,var) x 3 layers

// ---------------- prep: deg init, counts zero, pooled zero, BN scale/shift ----------------
__global__ void k_prep(BNParams bp) {
    int i = blockIdx.x * blockDim.x + threadIdx.x;
    if (i < NN) { g_dinv[i] = 1.0f; g_counts[i] = 0; }   // self-loop weight
    if (i < GG * 64) g_pooled[i] = 0.0f;
    if (i < 3 * 64) {
        int l = i >> 6, f = i & 63;
        const float* ga = bp.p[l * 4 + 0];
        const float* be = bp.p[l * 4 + 1];
        const float* mn = bp.p[l * 4 + 2];
        const float* va = bp.p[l * 4 + 3];
        float sc = ga[f] * rsqrtf(va[f] + 1e-5f);
        g_bnsc[l][f] = sc;
        g_bnsh[l][f] = be[f] - mn[f] * sc;
    }
}

// per-edge: weighted degree + incoming-count histogram
__global__ void k_degcount(const int* __restrict__ col, const float* __restrict__ w) {
    int e = blockIdx.x * blockDim.x + threadIdx.x;
    if (e >= EE) return;
    int c = col[e];
    atomicAdd(&g_dinv[c], w[e]);
    atomicAdd(&g_counts[c], 1);
}

// ---------------- 3-phase exclusive scan of counts -> offs ----------------
__global__ void k_scan1() {
    __shared__ int s[SCAN_B];
    int t = threadIdx.x;
    int i = blockIdx.x * SCAN_B + t;
    int val = (i < NN) ? g_counts[i] : 0;
    s[t] = val;
    __syncthreads();
#pragma unroll
    for (int off = 1; off < SCAN_B; off <<= 1) {
        int a = (t >= off) ? s[t - off] : 0;
        __syncthreads();
        s[t] += a;
        __syncthreads();
    }
    if (i < NN) g_offs[i] = s[t] - val;          // exclusive
    if (t == SCAN_B - 1) g_bsum[blockIdx.x] = s[t];
}

// parallel exclusive scan of the 98 block sums (single 128-thread block)
__global__ void k_scan2() {
    __shared__ int s[128];
    int t = threadIdx.x;
    int v = (t < SCAN_NBLK) ? g_bsum[t] : 0;
    s[t] = v;
    __syncthreads();
#pragma unroll
    for (int off = 1; off < 128; off <<= 1) {
        int a = (t >= off) ? s[t - off] : 0;
        __syncthreads();
        s[t] += a;
        __syncthreads();
    }
    if (t < SCAN_NBLK) g_bsum[t] = s[t] - v;     // exclusive
}

// add block offsets, init cursor, finalize dinv, set sentinel
__global__ void k_fix() {
    int i = blockIdx.x * blockDim.x + threadIdx.x;
    if (i < NN) {
        int o = g_offs[i] + g_bsum[i >> 10];
        g_offs[i] = o;
        g_cursor[i] = o;
        g_dinv[i] = rsqrtf(g_dinv[i]);
    }
    if (i == 0) g_offs[NN] = EE;
}

// scatter edges into dest-sorted order with fused norm
__global__ void k_scatter(const int* __restrict__ row, const int* __restrict__ col,
                          const float* __restrict__ w) {
    int e = blockIdx.x * blockDim.x + threadIdx.x;
    if (e >= EE) return;
    int r = row[e];
    int c = col[e];
    float nv = g_dinv[r] * w[e] * g_dinv[c];
    int pos = atomicAdd(&g_cursor[c], 1);
    g_payload[pos] = make_int2(r, __float_as_int(nv));
}

// ---------------- fused GEMM: out = act(in) @ W ; epilogue: bufA (fp16) + self-loop init (fp32) ----------------
template <int ACT>
__device__ __forceinline__ void gemm_body(const float* __restrict__ in,
                                          const float* __restrict__ W,
                                          const float* __restrict__ bias, int l) {
    __shared__ float sW[64 * 64];
    __shared__ float sIn[32][65];
    int t = threadIdx.x;  // 256 threads

    const float4* W4 = (const float4*)W;
    float4* sW4 = (float4*)sW;
#pragma unroll
    for (int i = 0; i < 4; i++) sW4[t + 256 * i] = W4[t + 256 * i];

    int r0 = blockIdx.x * 32;  // NN divisible by 32 -> no bounds checks
#pragma unroll
    for (int i = 0; i < 2; i++) {
        int idx = t + 256 * i;       // 0..511 float4s in 32x64 tile
        int rr = idx >> 4;
        int cc = (idx & 15) * 4;
        float4 v = *(const float4*)(in + (size_t)(r0 + rr) * 64 + cc);
        if (ACT == 1) {
            v.x = fmaxf(v.x, 0.f) * g_bnsc[l][cc + 0] + g_bnsh[l][cc + 0];
            v.y = fmaxf(v.y, 0.f) * g_bnsc[l][cc + 1] + g_bnsh[l][cc + 1];
            v.z = fmaxf(v.z, 0.f) * g_bnsc[l][cc + 2] + g_bnsh[l][cc + 2];
            v.w = fmaxf(v.w, 0.f) * g_bnsc[l][cc + 3] + g_bnsh[l][cc + 3];
        }
        sIn[rr][cc + 0] = v.x; sIn[rr][cc + 1] = v.y;
        sIn[rr][cc + 2] = v.z; sIn[rr][cc + 3] = v.w;
    }
    __syncthreads();

    int rowi = t >> 3;
    int c0 = (t & 7) * 4;        // lanes cover cols [c0, c0+3] and [c0+32, c0+35]
    float4 a0 = make_float4(0.f, 0.f, 0.f, 0.f);
    float4 a1 = make_float4(0.f, 0.f, 0.f, 0.f);
#pragma unroll
    for (int k = 0; k < 64; k++) {
        float a = sIn[rowi][k];
        float4 w0 = *(const float4*)&sW[k * 64 + c0];
        float4 w1 = *(const float4*)&sW[k * 64 + c0 + 32];
        a0.x += a * w0.x; a0.y += a * w0.y; a0.z += a * w0.z; a0.w += a * w0.w;
        a1.x += a * w1.x; a1.y += a * w1.y; a1.z += a * w1.z; a1.w += a * w1.w;
    }

    int gr = r0 + rowi;
    float dv = g_dinv[gr];
    float snv = dv * dv;                      // self-loop norm dinv^2
    float4 b0 = *(const float4*)(bias + c0);
    float4 b1 = *(const float4*)(bias + c0 + 32);
    size_t base = (size_t)gr * 64;

    // fp16 store of h (4 halves = 8B per segment)
    __half2 p00 = __floats2half2_rn(a0.x, a0.y);
    __half2 p01 = __floats2half2_rn(a0.z, a0.w);
    __half2 p10 = __floats2half2_rn(a1.x, a1.y);
    __half2 p11 = __floats2half2_rn(a1.z, a1.w);
    *(uint2*)&g_bufA[base + c0]      = make_uint2(*(unsigned*)&p00, *(unsigned*)&p01);
    *(uint2*)&g_bufA[base + c0 + 32] = make_uint2(*(unsigned*)&p10, *(unsigned*)&p11);

    float4 i0 = make_float4(a0.x * snv + b0.x, a0.y * snv + b0.y,
                            a0.z * snv + b0.z, a0.w * snv + b0.w);
    float4 i1 = make_float4(a1.x * snv + b1.x, a1.y * snv + b1.y,
                            a1.z * snv + b1.z, a1.w * snv + b1.w);
    *(float4*)&g_bufB[base + c0]      = i0;
    *(float4*)&g_bufB[base + c0 + 32] = i1;
}

__global__ void __launch_bounds__(256) k_gemm1(const float* __restrict__ x,
                                               const float* __restrict__ W,
                                               const float* __restrict__ b) {
    gemm_body<0>(x, W, b, 0);
}
__global__ void __launch_bounds__(256) k_gemm23(const float* __restrict__ W,
                                                const float* __restrict__ b, int l) {
    gemm_body<1>(g_bufB, W, b, l);
}

// ---------------- CSR aggregation: bufB[c] = selfinit[c] + sum_e norm_e * half(bufA[src_e]) ----------------
// 8 lanes per destination; lane q owns 8 features (16B of fp16) = uint4.
__global__ void __launch_bounds__(256) k_agg() {
    int t = threadIdx.x;
    int q = t & 7;
    int c = blockIdx.x * 32 + (t >> 3);      // NN % 32 == 0 -> no bounds check
    int e = g_offs[c];
    int end = g_offs[c + 1];

    const uint4* __restrict__ A4 = (const uint4*)g_bufA;   // 8 uint4 per row
    float4* B4 = (float4*)g_bufB;                          // 16 float4 per row

    size_t bidx = (size_t)c * 16 + (size_t)q * 2;
    float4 acc0 = B4[bidx];
    float4 acc1 = B4[bidx + 1];

    // unroll-by-2 for MLP on the payload->gather chain
    for (; e + 1 < end; e += 2) {
        int2 p0 = __ldg(&g_payload[e]);
        int2 p1 = __ldg(&g_payload[e + 1]);
        uint4 r0 = __ldg(&A4[(size_t)p0.x * 8 + q]);
        uint4 r1 = __ldg(&A4[(size_t)p1.x * 8 + q]);
        float n0 = __int_as_float(p0.y);
        float n1 = __int_as_float(p1.y);
        float2 f;
        f = __half22float2(*(__half2*)&r0.x); acc0.x += f.x * n0; acc0.y += f.y * n0;
        f = __half22float2(*(__half2*)&r0.y); acc0.z += f.x * n0; acc0.w += f.y * n0;
        f = __half22float2(*(__half2*)&r0.z); acc1.x += f.x * n0; acc1.y += f.y * n0;
        f = __half22float2(*(__half2*)&r0.w); acc1.z += f.x * n0; acc1.w += f.y * n0;
        f = __half22float2(*(__half2*)&r1.x); acc0.x += f.x * n1; acc0.y += f.y * n1;
        f = __half22float2(*(__half2*)&r1.y); acc0.z += f.x * n1; acc0.w += f.y * n1;
        f = __half22float2(*(__half2*)&r1.z); acc1.x += f.x * n1; acc1.y += f.y * n1;
        f = __half22float2(*(__half2*)&r1.w); acc1.z += f.x * n1; acc1.w += f.y * n1;
    }
    if (e < end) {
        int2 p0 = __ldg(&g_payload[e]);
        uint4 r0 = __ldg(&A4[(size_t)p0.x * 8 + q]);
        float n0 = __int_as_float(p0.y);
        float2 f;
        f = __half22float2(*(__half2*)&r0.x); acc0.x += f.x * n0; acc0.y += f.y * n0;
        f = __half22float2(*(__half2*)&r0.y); acc0.z += f.x * n0; acc0.w += f.y * n0;
        f = __half22float2(*(__half2*)&r0.z); acc1.x += f.x * n0; acc1.y += f.y * n0;
        f = __half22float2(*(__half2*)&r0.w); acc1.z += f.x * n0; acc1.w += f.y * n0;
    }
    B4[bidx]     = acc0;
    B4[bidx + 1] = acc1;
}

// ---------------- BN3 + global_add_pool (batch is sorted: run-accumulate) ----------------
#define POOL_CHUNK 128
__global__ void k_pool(const int* __restrict__ batch) {
    int f = threadIdx.x;  // 64 threads: one per feature
    int start = blockIdx.x * POOL_CHUNK;
    int end = start + POOL_CHUNK;
    if (end > NN) end = NN;
    if (start >= NN) return;
    float sc = g_bnsc[2][f], sh = g_bnsh[2][f];
    int cur = batch[start];
    float acc = 0.f;
    for (int n = start; n < end; n++) {
        int b = batch[n];
        if (b != cur) {
            atomicAdd(&g_pooled[cur * 64 + f], acc);
            acc = 0.f;
            cur = b;
        }
        acc += g_bufB[(size_t)n * 64 + f] * sc + sh;
    }
    atomicAdd(&g_pooled[cur * 64 + f], acc);
}

// ---------------- FC: out[g] = relu(pooled[g]) . Wfc + bfc ----------------
__global__ void k_fc(const float* __restrict__ Wfc, const float* __restrict__ bfc,
                     float* __restrict__ out) {
    int g = threadIdx.x;  // 128
    float acc = 0.f;
#pragma unroll
    for (int k = 0; k < 64; k++)
        acc += fmaxf(g_pooled[g * 64 + k], 0.f) * Wfc[k];
    out[g] = acc + bfc[0];
}

// ---------------- launch ----------------
extern "C" void kernel_launch(void* const* d_in, const int* in_sizes, int n_in,
                              void* d_out, int out_size) {
    const float* x     = (const float*)d_in[0];
    const int*   ei    = (const int*)d_in[1];
    const int*   row   = ei;
    const int*   col   = ei + EE;
    const float* ew    = (const float*)d_in[2];
    const int*   batch = (const int*)d_in[3];
    const float* W1 = (const float*)d_in[4];
    const float* b1 = (const float*)d_in[5];
    const float* W2 = (const float*)d_in[6];
    const float* b2 = (const float*)d_in[7];
    const float* W3 = (const float*)d_in[8];
    const float* b3 = (const float*)d_in[9];
    const float* Wfc = (const float*)d_in[10];
    const float* bfc = (const float*)d_in[11];

    BNParams bp;
    for (int i = 0; i < 12; i++) bp.p[i] = (const float*)d_in[12 + i];

    int nb_n = (NN + 255) / 256;          // 391
    int nb_e = (EE + 255) / 256;          // 6250
    int nb_gemm = NN / 32;                // 3125
    int nb_agg = NN / 32;                 // 3125
    int nb_pool = (NN + POOL_CHUNK - 1) / POOL_CHUNK; // 782

    // CSR build + norm precompute
    k_prep<<<nb_n, 256>>>(bp);
    k_degcount<<<nb_e, 256>>>(col, ew);
    k_scan1<<<SCAN_NBLK, SCAN_B>>>();
    k_scan2<<<1, 128>>>();
    k_fix<<<nb_n, 256>>>();
    k_scatter<<<nb_e, 256>>>(row, col, ew);

    // layer 1
    k_gemm1<<<nb_gemm, 256>>>(x, W1, b1);
    k_agg<<<nb_agg, 256>>>();
    // layer 2 (relu + bn1 fused into gemm input)
    k_gemm23<<<nb_gemm, 256>>>(W2, b2, 0);
    k_agg<<<nb_agg, 256>>>();
    // layer 3 (relu + bn2 fused into gemm input)
    k_gemm23<<<nb_gemm, 256>>>(W3, b3, 1);
    k_agg<<<nb_agg, 256>>>();

    // bn3 (no relu) + pool, then fc
    k_pool<<<nb_pool, 64>>>(batch);
    k_fc<<<1, 128>>>(Wfc, bfc, (float*)d_out);
}

// round 5
// speedup vs baseline: 1.8197x; 1.3167x over previous
#include <cuda_runtime.h>
#include <cuda_fp16.h>

#define NN 100000
#define EE 1600000
#define GG 128
#define SCAN_B 1024
#define SCAN_NBLK ((NN + SCAN_B - 1) / SCAN_B)   // 98
#define GR 128   // gemm rows per block
#define SIS 132  // sInT stride (multiple of 4 -> 16B-aligned float4 rows)

// ---------------- scratch (static device globals; no allocation) ----------------
__device__ __align__(16) float g_dinv[NN];              // weighted deg -> dinv in place
__device__ __align__(16) int   g_counts[NN];
__device__ __align__(16) int   g_offs[NN + 1];
__device__ __align__(16) int   g_cursor[NN];
__device__ __align__(16) int   g_bsum[SCAN_NBLK + 1];
__device__ __align__(16) int2  g_payload[EE];           // {src, norm-as-bits} sorted by dest
__device__ __align__(16) __half g_bufA[(size_t)NN * 64]; // h (gemm output, fp16)
__device__ __align__(16) float g_bufB[(size_t)NN * 64]; // self-loop init / agg result (fp32)
__device__ __align__(16) float g_pooled[GG * 64];
__device__ __align__(16) float g_bnsc[3][64];
__device__ __align__(16) float g_bnsh[3][64];

struct BNParams { const float* p[12]; };  // (gamma,beta,mean,var) x 3 layers

__device__ __forceinline__ unsigned long long ffma2(unsigned long long a,
                                                    unsigned long long b,
                                                    unsigned long long c) {
    unsigned long long d;
    asm("fma.rn.f32x2 %0, %1, %2, %3;" : "=l"(d) : "l"(a), "l"(b), "l"(c));
    return d;
}
__device__ __forceinline__ unsigned long long rep2(float a) {
    unsigned long long d;
    unsigned ai = __float_as_uint(a);
    asm("mov.b64 %0, {%1, %1};" : "=l"(d) : "r"(ai));
    return d;
}

// ---------------- prep: deg init, counts zero, pooled zero, BN scale/shift ----------------
__global__ void k_prep(BNParams bp) {
    int i = blockIdx.x * blockDim.x + threadIdx.x;
    if (i < NN) { g_dinv[i] = 1.0f; g_counts[i] = 0; }   // self-loop weight
    if (i < GG * 64) g_pooled[i] = 0.0f;
    if (i < 3 * 64) {
        int l = i >> 6, f = i & 63;
        const float* ga = bp.p[l * 4 + 0];
        const float* be = bp.p[l * 4 + 1];
        const float* mn = bp.p[l * 4 + 2];
        const float* va = bp.p[l * 4 + 3];
        float sc = ga[f] * rsqrtf(va[f] + 1e-5f);
        g_bnsc[l][f] = sc;
        g_bnsh[l][f] = be[f] - mn[f] * sc;
    }
}

// per-edge: weighted degree + incoming-count histogram
__global__ void k_degcount(const int* __restrict__ col, const float* __restrict__ w) {
    int e = blockIdx.x * blockDim.x + threadIdx.x;
    if (e >= EE) return;
    int c = col[e];
    atomicAdd(&g_dinv[c], w[e]);
    atomicAdd(&g_counts[c], 1);
}

// ---------------- 3-phase exclusive scan of counts -> offs ----------------
__global__ void k_scan1() {
    __shared__ int s[SCAN_B];
    int t = threadIdx.x;
    int i = blockIdx.x * SCAN_B + t;
    int val = (i < NN) ? g_counts[i] : 0;
    s[t] = val;
    __syncthreads();
#pragma unroll
    for (int off = 1; off < SCAN_B; off <<= 1) {
        int a = (t >= off) ? s[t - off] : 0;
        __syncthreads();
        s[t] += a;
        __syncthreads();
    }
    if (i < NN) g_offs[i] = s[t] - val;          // exclusive
    if (t == SCAN_B - 1) g_bsum[blockIdx.x] = s[t];
}

// single-warp shfl scan over 98 block sums (ceil(98/32)=4 chunks, serial carry)
__global__ void k_scan2() {
    int t = threadIdx.x;          // 32 threads
    int carry = 0;
    for (int base = 0; base < SCAN_NBLK; base += 32) {
        int i = base + t;
        int v = (i < SCAN_NBLK) ? g_bsum[i] : 0;
        int x = v;
#pragma unroll
        for (int off = 1; off < 32; off <<= 1) {
            int y = __shfl_up_sync(0xFFFFFFFF, x, off);
            if (t >= off) x += y;
        }
        if (i < SCAN_NBLK) g_bsum[i] = carry + x - v;   // exclusive
        carry += __shfl_sync(0xFFFFFFFF, x, 31);
    }
}

// add block offsets, init cursor, finalize dinv, set sentinel
__global__ void k_fix() {
    int i = blockIdx.x * blockDim.x + threadIdx.x;
    if (i < NN) {
        int o = g_offs[i] + g_bsum[i >> 10];
        g_offs[i] = o;
        g_cursor[i] = o;
        g_dinv[i] = rsqrtf(g_dinv[i]);
    }
    if (i == 0) g_offs[NN] = EE;
}

// scatter edges into dest-sorted order with fused norm
__global__ void k_scatter(const int* __restrict__ row, const int* __restrict__ col,
                          const float* __restrict__ w) {
    int e = blockIdx.x * blockDim.x + threadIdx.x;
    if (e >= EE) return;
    int r = row[e];
    int c = col[e];
    float nv = g_dinv[r] * w[e] * g_dinv[c];
    int pos = atomicAdd(&g_cursor[c], 1);
    g_payload[pos] = make_int2(r, __float_as_int(nv));
}

// ---------------- register-blocked GEMM with packed f32x2 FMA ----------------
// 128 threads, tile GR=128 rows x 64 cols; micro 8 rows x 8 cols per thread.
// epilogue: bufA (fp16 h), bufB (fp32 self-loop init = h*dinv^2 + bias)
template <int ACT>
__device__ __forceinline__ void gemm_body(const float* __restrict__ in,
                                          const float* __restrict__ W,
                                          const float* __restrict__ bias, int l) {
    __shared__ __align__(16) float sW[64 * 64];          // [k][c]
    __shared__ __align__(16) float sInT[64 * SIS];       // [k][r], padded (SIS % 4 == 0)
    int t = threadIdx.x;  // 128

    const float4* W4 = (const float4*)W;
    float4* sW4 = (float4*)sW;
#pragma unroll
    for (int i = 0; i < 8; i++) sW4[t + 128 * i] = W4[t + 128 * i];

    int r0 = blockIdx.x * GR;
#pragma unroll
    for (int i = 0; i < 16; i++) {
        int idx = t + 128 * i;        // 0..2047 float4s in 128x64 tile
        int rr = idx >> 4;
        int cc = (idx & 15) * 4;
        int gr = r0 + rr;
        float4 v = make_float4(0.f, 0.f, 0.f, 0.f);
        if (gr < NN) v = *(const float4*)(in + (size_t)gr * 64 + cc);
        if (ACT == 1) {
            v.x = fmaxf(v.x, 0.f) * g_bnsc[l][cc + 0] + g_bnsh[l][cc + 0];
            v.y = fmaxf(v.y, 0.f) * g_bnsc[l][cc + 1] + g_bnsh[l][cc + 1];
            v.z = fmaxf(v.z, 0.f) * g_bnsc[l][cc + 2] + g_bnsh[l][cc + 2];
            v.w = fmaxf(v.w, 0.f) * g_bnsc[l][cc + 3] + g_bnsh[l][cc + 3];
        }
        sInT[(cc + 0) * SIS + rr] = v.x;
        sInT[(cc + 1) * SIS + rr] = v.y;
        sInT[(cc + 2) * SIS + rr] = v.z;
        sInT[(cc + 3) * SIS + rr] = v.w;
    }
    __syncthreads();

    int tr = t >> 3;                  // 0..15 row group
    int tc = t & 7;                   // 0..7  col group
    int rbase = tr * 8;
    int cbase = tc * 8;

    unsigned long long acc[8][4];
#pragma unroll
    for (int r = 0; r < 8; r++)
#pragma unroll
        for (int j = 0; j < 4; j++) acc[r][j] = 0ull;   // {0.f,0.f}

#pragma unroll
    for (int k = 0; k < 64; k++) {
        float4 a0 = *(const float4*)&sInT[k * SIS + rbase];      // 16B-aligned: SIS%4==0, rbase%8==0
        float4 a1 = *(const float4*)&sInT[k * SIS + rbase + 4];
        ulonglong2 wlo = *(const ulonglong2*)&sW[k * 64 + cbase];      // cols c..c+3
        ulonglong2 whi = *(const ulonglong2*)&sW[k * 64 + cbase + 4];  // cols c+4..c+7
        unsigned long long ap[8];
        ap[0] = rep2(a0.x); ap[1] = rep2(a0.y); ap[2] = rep2(a0.z); ap[3] = rep2(a0.w);
        ap[4] = rep2(a1.x); ap[5] = rep2(a1.y); ap[6] = rep2(a1.z); ap[7] = rep2(a1.w);
#pragma unroll
        for (int r = 0; r < 8; r++) {
            acc[r][0] = ffma2(ap[r], wlo.x, acc[r][0]);
            acc[r][1] = ffma2(ap[r], wlo.y, acc[r][1]);
            acc[r][2] = ffma2(ap[r], whi.x, acc[r][2]);
            acc[r][3] = ffma2(ap[r], whi.y, acc[r][3]);
        }
    }

    float4 bl = *(const float4*)(bias + cbase);
    float4 bh = *(const float4*)(bias + cbase + 4);
#pragma unroll
    for (int r = 0; r < 8; r++) {
        int gr = r0 + rbase + r;
        if (gr >= NN) break;
        float2 c0 = *(float2*)&acc[r][0];
        float2 c1 = *(float2*)&acc[r][1];
        float2 c2 = *(float2*)&acc[r][2];
        float2 c3 = *(float2*)&acc[r][3];
        size_t base = (size_t)gr * 64 + cbase;

        // fp16 h store (8 halves = 16B)
        __half2 h0 = __floats2half2_rn(c0.x, c0.y);
        __half2 h1 = __floats2half2_rn(c1.x, c1.y);
        __half2 h2 = __floats2half2_rn(c2.x, c2.y);
        __half2 h3 = __floats2half2_rn(c3.x, c3.y);
        *(uint4*)&g_bufA[base] = make_uint4(*(unsigned*)&h0, *(unsigned*)&h1,
                                            *(unsigned*)&h2, *(unsigned*)&h3);

        float dv = g_dinv[gr];
        float snv = dv * dv;
        float4 o0 = make_float4(c0.x * snv + bl.x, c0.y * snv + bl.y,
                                c1.x * snv + bl.z, c1.y * snv + bl.w);
        float4 o1 = make_float4(c2.x * snv + bh.x, c2.y * snv + bh.y,
                                c3.x * snv + bh.z, c3.y * snv + bh.w);
        *(float4*)&g_bufB[base]     = o0;
        *(float4*)&g_bufB[base + 4] = o1;
    }
}

__global__ void __launch_bounds__(128) k_gemm1(const float* __restrict__ x,
                                               const float* __restrict__ W,
                                               const float* __restrict__ b) {
    gemm_body<0>(x, W, b, 0);
}
__global__ void __launch_bounds__(128) k_gemm23(const float* __restrict__ W,
                                                const float* __restrict__ b, int l) {
    gemm_body<1>(g_bufB, W, b, l);
}

// ---------------- CSR aggregation: bufB[c] = selfinit[c] + sum_e norm_e * half(bufA[src_e]) ----------------
// 8 lanes per destination; lane q owns 8 features (16B of fp16) = uint4.
__global__ void __launch_bounds__(256) k_agg() {
    int t = threadIdx.x;
    int q = t & 7;
    int c = blockIdx.x * 32 + (t >> 3);      // NN % 32 == 0 -> no bounds check
    int e = g_offs[c];
    int end = g_offs[c + 1];

    const uint4* __restrict__ A4 = (const uint4*)g_bufA;   // 8 uint4 per row
    float4* B4 = (float4*)g_bufB;                          // 16 float4 per row

    size_t bidx = (size_t)c * 16 + (size_t)q * 2;
    float4 acc0 = B4[bidx];
    float4 acc1 = B4[bidx + 1];

    for (; e + 1 < end; e += 2) {
        int2 p0 = __ldg(&g_payload[e]);
        int2 p1 = __ldg(&g_payload[e + 1]);
        uint4 r0 = __ldg(&A4[(size_t)p0.x * 8 + q]);
        uint4 r1 = __ldg(&A4[(size_t)p1.x * 8 + q]);
        float n0 = __int_as_float(p0.y);
        float n1 = __int_as_float(p1.y);
        float2 f;
        f = __half22float2(*(__half2*)&r0.x); acc0.x += f.x * n0; acc0.y += f.y * n0;
        f = __half22float2(*(__half2*)&r0.y); acc0.z += f.x * n0; acc0.w += f.y * n0;
        f = __half22float2(*(__half2*)&r0.z); acc1.x += f.x * n0; acc1.y += f.y * n0;
        f = __half22float2(*(__half2*)&r0.w); acc1.z += f.x * n0; acc1.w += f.y * n0;
        f = __half22float2(*(__half2*)&r1.x); acc0.x += f.x * n1; acc0.y += f.y * n1;
        f = __half22float2(*(__half2*)&r1.y); acc0.z += f.x * n1; acc0.w += f.y * n1;
        f = __half22float2(*(__half2*)&r1.z); acc1.x += f.x * n1; acc1.y += f.y * n1;
        f = __half22float2(*(__half2*)&r1.w); acc1.z += f.x * n1; acc1.w += f.y * n1;
    }
    if (e < end) {
        int2 p0 = __ldg(&g_payload[e]);
        uint4 r0 = __ldg(&A4[(size_t)p0.x * 8 + q]);
        float n0 = __int_as_float(p0.y);
        float2 f;
        f = __half22float2(*(__half2*)&r0.x); acc0.x += f.x * n0; acc0.y += f.y * n0;
        f = __half22float2(*(__half2*)&r0.y); acc0.z += f.x * n0; acc0.w += f.y * n0;
        f = __half22float2(*(__half2*)&r0.z); acc1.x += f.x * n0; acc1.y += f.y * n0;
        f = __half22float2(*(__half2*)&r0.w); acc1.z += f.x * n0; acc1.w += f.y * n0;
    }
    B4[bidx]     = acc0;
    B4[bidx + 1] = acc1;
}

// ---------------- BN3 + global_add_pool (batch is sorted: run-accumulate) ----------------
#define POOL_CHUNK 128
__global__ void k_pool(const int* __restrict__ batch) {
    int f = threadIdx.x;  // 64 threads: one per feature
    int start = blockIdx.x * POOL_CHUNK;
    int end = start + POOL_CHUNK;
    if (end > NN) end = NN;
    if (start >= NN) return;
    float sc = g_bnsc[2][f], sh = g_bnsh[2][f];
    int cur = batch[start];
    float acc = 0.f;
    for (int n = start; n < end; n++) {
        int b = batch[n];
        if (b != cur) {
            atomicAdd(&g_pooled[cur * 64 + f], acc);
            acc = 0.f;
            cur = b;
        }
        acc += g_bufB[(size_t)n * 64 + f] * sc + sh;
    }
    atomicAdd(&g_pooled[cur * 64 + f], acc);
}

// ---------------- FC: out[g] = relu(pooled[g]) . Wfc + bfc ----------------
__global__ void k_fc(const float* __restrict__ Wfc, const float* __restrict__ bfc,
                     float* __restrict__ out) {
    int g = threadIdx.x;  // 128
    float acc = 0.f;
#pragma unroll
    for (int k = 0; k < 64; k++)
        acc += fmaxf(g_pooled[g * 64 + k], 0.f) * Wfc[k];
    out[g] = acc + bfc[0];
}

// ---------------- launch ----------------
extern "C" void kernel_launch(void* const* d_in, const int* in_sizes, int n_in,
                              void* d_out, int out_size) {
    const float* x     = (const float*)d_in[0];
    const int*   ei    = (const int*)d_in[1];
    const int*   row   = ei;
    const int*   col   = ei + EE;
    const float* ew    = (const float*)d_in[2];
    const int*   batch = (const int*)d_in[3];
    const float* W1 = (const float*)d_in[4];
    const float* b1 = (const float*)d_in[5];
    const float* W2 = (const float*)d_in[6];
    const float* b2 = (const float*)d_in[7];
    const float* W3 = (const float*)d_in[8];
    const float* b3 = (const float*)d_in[9];
    const float* Wfc = (const float*)d_in[10];
    const float* bfc = (const float*)d_in[11];

    BNParams bp;
    for (int i = 0; i < 12; i++) bp.p[i] = (const float*)d_in[12 + i];

    int nb_n = (NN + 255) / 256;          // 391
    int nb_e = (EE + 255) / 256;          // 6250
    int nb_gemm = (NN + GR - 1) / GR;     // 782
    int nb_agg = NN / 32;                 // 3125
    int nb_pool = (NN + POOL_CHUNK - 1) / POOL_CHUNK; // 782

    // CSR build + norm precompute
    k_prep<<<nb_n, 256>>>(bp);
    k_degcount<<<nb_e, 256>>>(col, ew);
    k_scan1<<<SCAN_NBLK, SCAN_B>>>();
    k_scan2<<<1, 32>>>();
    k_fix<<<nb_n, 256>>>();
    k_scatter<<<nb_e, 256>>>(row, col, ew);

    // layer 1
    k_gemm1<<<nb_gemm, 128>>>(x, W1, b1);
    k_agg<<<nb_agg, 256>>>();
    // layer 2 (relu + bn1 fused into gemm input)
    k_gemm23<<<nb_gemm, 128>>>(W2, b2, 0);
    k_agg<<<nb_agg, 256>>>();
    // layer 3 (relu + bn2 fused into gemm input)
    k_gemm23<<<nb_gemm, 128>>>(W3, b3, 1);
    k_agg<<<nb_agg, 256>>>();

    // bn3 (no relu) + pool, then fc
    k_pool<<<nb_pool, 64>>>(batch);
    k_fc<<<1, 128>>>(Wfc, bfc, (float*)d_out);
}

// round 6
// speedup vs baseline: 1.8383x; 1.0103x over previous
#include <cuda_runtime.h>
#include <cuda_fp16.h>

#define NN 100000
#define EE 1600000
#define GG 128
#define SCAN_B 1024
#define SCAN_NBLK ((NN + SCAN_B - 1) / SCAN_B)   // 98
#define GR 128   // gemm rows per block
#define SIS 132  // sInT stride (multiple of 4 -> 16B-aligned float4 rows)

// ---------------- scratch (static device globals; no allocation) ----------------
__device__ __align__(16) unsigned long long g_degcnt[NN]; // count<<48 | wdeg*2^32
__device__ __align__(16) float g_dinv[NN];
__device__ __align__(16) int   g_offs[NN + 1];
__device__ __align__(16) int   g_cursor[NN];
__device__ __align__(16) int   g_bsum[SCAN_NBLK + 1];
__device__ __align__(16) int2  g_payload[EE];           // {src, (w*dinv[src])-as-bits} sorted by dest
__device__ __align__(16) __half g_bufA[(size_t)NN * 64]; // h (gemm output, fp16)
__device__ __align__(16) float g_bufB[(size_t)NN * 64]; // conv output (fp32)
__device__ __align__(16) float g_pooled[GG * 64];
__device__ __align__(16) float g_bnsc[3][64];
__device__ __align__(16) float g_bnsh[3][64];

struct BNParams { const float* p[12]; };  // (gamma,beta,mean,var) x 3 layers

__device__ __forceinline__ unsigned long long ffma2(unsigned long long a,
                                                    unsigned long long b,
                                                    unsigned long long c) {
    unsigned long long d;
    asm("fma.rn.f32x2 %0, %1, %2, %3;" : "=l"(d) : "l"(a), "l"(b), "l"(c));
    return d;
}
__device__ __forceinline__ unsigned long long rep2(float a) {
    unsigned long long d;
    unsigned ai = __float_as_uint(a);
    asm("mov.b64 %0, {%1, %1};" : "=l"(d) : "r"(ai));
    return d;
}

// ---------------- prep: degcnt init (self-loop weight 1.0), pooled zero, BN scale/shift ----------------
__global__ void k_prep(BNParams bp) {
    int i = blockIdx.x * blockDim.x + threadIdx.x;
    if (i < NN) g_degcnt[i] = 1ULL << 32;      // weight 1.0 fixed-point, count 0
    if (i < GG * 64) g_pooled[i] = 0.0f;
    if (i < 3 * 64) {
        int l = i >> 6, f = i & 63;
        const float* ga = bp.p[l * 4 + 0];
        const float* be = bp.p[l * 4 + 1];
        const float* mn = bp.p[l * 4 + 2];
        const float* va = bp.p[l * 4 + 3];
        float sc = ga[f] * rsqrtf(va[f] + 1e-5f);
        g_bnsc[l][f] = sc;
        g_bnsh[l][f] = be[f] - mn[f] * sc;
    }
}

// per-edge: one packed 64-bit atomic (count + fixed-point weighted degree)
__global__ void k_degcount(const int* __restrict__ col, const float* __restrict__ w) {
    int e = blockIdx.x * blockDim.x + threadIdx.x;
    if (e >= EE) return;
    unsigned long long pack = (1ULL << 48) + (unsigned long long)(w[e] * 4294967296.0f);
    atomicAdd(&g_degcnt[col[e]], pack);
}

// ---------------- 3-phase exclusive scan of counts -> offs ----------------
__global__ void k_scan1() {
    __shared__ int s[SCAN_B];
    int t = threadIdx.x;
    int i = blockIdx.x * SCAN_B + t;
    int val = (i < NN) ? (int)(g_degcnt[i] >> 48) : 0;
    s[t] = val;
    __syncthreads();
#pragma unroll
    for (int off = 1; off < SCAN_B; off <<= 1) {
        int a = (t >= off) ? s[t - off] : 0;
        __syncthreads();
        s[t] += a;
        __syncthreads();
    }
    if (i < NN) g_offs[i] = s[t] - val;          // exclusive
    if (t == SCAN_B - 1) g_bsum[blockIdx.x] = s[t];
}

// single-warp shfl scan over 98 block sums
__global__ void k_scan2() {
    int t = threadIdx.x;          // 32 threads
    int carry = 0;
    for (int base = 0; base < SCAN_NBLK; base += 32) {
        int i = base + t;
        int v = (i < SCAN_NBLK) ? g_bsum[i] : 0;
        int x = v;
#pragma unroll
        for (int off = 1; off < 32; off <<= 1) {
            int y = __shfl_up_sync(0xFFFFFFFF, x, off);
            if (t >= off) x += y;
        }
        if (i < SCAN_NBLK) g_bsum[i] = carry + x - v;   // exclusive
        carry += __shfl_sync(0xFFFFFFFF, x, 31);
    }
}

// add block offsets, init cursor, finalize dinv, set sentinel
__global__ void k_fix() {
    int i = blockIdx.x * blockDim.x + threadIdx.x;
    if (i < NN) {
        int o = g_offs[i] + g_bsum[i >> 10];
        g_offs[i] = o;
        g_cursor[i] = o;
        float deg = (float)(g_degcnt[i] & 0xFFFFFFFFFFFFULL) * (1.0f / 4294967296.0f);
        g_dinv[i] = rsqrtf(deg);
    }
    if (i == 0) g_offs[NN] = EE;
}

// scatter edges into dest-sorted order; payload = {src, w*dinv[src]}
__global__ void k_scatter(const int* __restrict__ row, const int* __restrict__ col,
                          const float* __restrict__ w) {
    int e = blockIdx.x * blockDim.x + threadIdx.x;
    if (e >= EE) return;
    int r = row[e];
    int c = col[e];
    float nv = g_dinv[r] * w[e];
    int pos = atomicAdd(&g_cursor[c], 1);
    g_payload[pos] = make_int2(r, __float_as_int(nv));
}

// ---------------- register-blocked GEMM with packed f32x2 FMA ----------------
// 128 threads, tile GR=128 rows x 64 cols; micro 8 rows x 8 cols per thread.
// epilogue: bufA (fp16 h) only.
template <int ACT>
__device__ __forceinline__ void gemm_body(const float* __restrict__ in,
                                          const float* __restrict__ W, int l) {
    __shared__ __align__(16) float sW[64 * 64];          // [k][c]
    __shared__ __align__(16) float sInT[64 * SIS];       // [k][r], padded (SIS % 4 == 0)
    int t = threadIdx.x;  // 128

    const float4* W4 = (const float4*)W;
    float4* sW4 = (float4*)sW;
#pragma unroll
    for (int i = 0; i < 8; i++) sW4[t + 128 * i] = W4[t + 128 * i];

    int r0 = blockIdx.x * GR;
#pragma unroll
    for (int i = 0; i < 16; i++) {
        int idx = t + 128 * i;        // 0..2047 float4s in 128x64 tile
        int rr = idx >> 4;
        int cc = (idx & 15) * 4;
        int gr = r0 + rr;
        float4 v = make_float4(0.f, 0.f, 0.f, 0.f);
        if (gr < NN) v = *(const float4*)(in + (size_t)gr * 64 + cc);
        if (ACT == 1) {
            v.x = fmaxf(v.x, 0.f) * g_bnsc[l][cc + 0] + g_bnsh[l][cc + 0];
            v.y = fmaxf(v.y, 0.f) * g_bnsc[l][cc + 1] + g_bnsh[l][cc + 1];
            v.z = fmaxf(v.z, 0.f) * g_bnsc[l][cc + 2] + g_bnsh[l][cc + 2];
            v.w = fmaxf(v.w, 0.f) * g_bnsc[l][cc + 3] + g_bnsh[l][cc + 3];
        }
        sInT[(cc + 0) * SIS + rr] = v.x;
        sInT[(cc + 1) * SIS + rr] = v.y;
        sInT[(cc + 2) * SIS + rr] = v.z;
        sInT[(cc + 3) * SIS + rr] = v.w;
    }
    __syncthreads();

    int tr = t >> 3;                  // 0..15 row group
    int tc = t & 7;                   // 0..7  col group
    int rbase = tr * 8;
    int cbase = tc * 8;

    unsigned long long acc[8][4];
#pragma unroll
    for (int r = 0; r < 8; r++)
#pragma unroll
        for (int j = 0; j < 4; j++) acc[r][j] = 0ull;

#pragma unroll
    for (int k = 0; k < 64; k++) {
        float4 a0 = *(const float4*)&sInT[k * SIS + rbase];
        float4 a1 = *(const float4*)&sInT[k * SIS + rbase + 4];
        ulonglong2 wlo = *(const ulonglong2*)&sW[k * 64 + cbase];
        ulonglong2 whi = *(const ulonglong2*)&sW[k * 64 + cbase + 4];
        unsigned long long ap[8];
        ap[0] = rep2(a0.x); ap[1] = rep2(a0.y); ap[2] = rep2(a0.z); ap[3] = rep2(a0.w);
        ap[4] = rep2(a1.x); ap[5] = rep2(a1.y); ap[6] = rep2(a1.z); ap[7] = rep2(a1.w);
#pragma unroll
        for (int r = 0; r < 8; r++) {
            acc[r][0] = ffma2(ap[r], wlo.x, acc[r][0]);
            acc[r][1] = ffma2(ap[r], wlo.y, acc[r][1]);
            acc[r][2] = ffma2(ap[r], whi.x, acc[r][2]);
            acc[r][3] = ffma2(ap[r], whi.y, acc[r][3]);
        }
    }

#pragma unroll
    for (int r = 0; r < 8; r++) {
        int gr = r0 + rbase + r;
        if (gr >= NN) break;
        float2 c0 = *(float2*)&acc[r][0];
        float2 c1 = *(float2*)&acc[r][1];
        float2 c2 = *(float2*)&acc[r][2];
        float2 c3 = *(float2*)&acc[r][3];
        __half2 h0 = __floats2half2_rn(c0.x, c0.y);
        __half2 h1 = __floats2half2_rn(c1.x, c1.y);
        __half2 h2 = __floats2half2_rn(c2.x, c2.y);
        __half2 h3 = __floats2half2_rn(c3.x, c3.y);
        *(uint4*)&g_bufA[(size_t)gr * 64 + cbase] =
            make_uint4(*(unsigned*)&h0, *(unsigned*)&h1,
                       *(unsigned*)&h2, *(unsigned*)&h3);
    }
}

__global__ void __launch_bounds__(128) k_gemm1(const float* __restrict__ x,
                                               const float* __restrict__ W) {
    gemm_body<0>(x, W, 0);
}
__global__ void __launch_bounds__(128) k_gemm23(const float* __restrict__ W, int l) {
    gemm_body<1>(g_bufB, W, l);
}

// ---------------- CSR aggregation (warp per destination) ----------------
// bufB[c] = dinv[c] * sum_e (w_e*dinv[src_e]) * h16[src_e] + dinv[c]^2 * h16[c] + bias
// 32-lane warp: two 16-lane halves take alternating edges; lane q owns 8B (4 features).
__global__ void __launch_bounds__(256) k_agg(const float* __restrict__ bias) {
    int warp = threadIdx.x >> 5;
    int lane = threadIdx.x & 31;
    int c = blockIdx.x * 8 + warp;          // NN % 8 == 0
    int half = lane >> 4;
    int q = lane & 15;
    int e = g_offs[c] + half;
    int end = g_offs[c + 1];

    const uint2* __restrict__ A2 = (const uint2*)g_bufA;   // 16 uint2 per 64-feat row

    float4 acc = make_float4(0.f, 0.f, 0.f, 0.f);
    for (; e < end; e += 2) {
        int2 p = __ldg(&g_payload[e]);
        uint2 r = __ldg(&A2[(size_t)p.x * 16 + q]);
        float n = __int_as_float(p.y);
        float2 f0 = __half22float2(*(__half2*)&r.x);
        float2 f1 = __half22float2(*(__half2*)&r.y);
        acc.x += f0.x * n; acc.y += f0.y * n;
        acc.z += f1.x * n; acc.w += f1.y * n;
    }
    acc.x += __shfl_xor_sync(0xFFFFFFFFu, acc.x, 16);
    acc.y += __shfl_xor_sync(0xFFFFFFFFu, acc.y, 16);
    acc.z += __shfl_xor_sync(0xFFFFFFFFu, acc.z, 16);
    acc.w += __shfl_xor_sync(0xFFFFFFFFu, acc.w, 16);

    if (half == 0) {
        float dv = g_dinv[c];
        float snv = dv * dv;
        uint2 sr = __ldg(&A2[(size_t)c * 16 + q]);
        float2 s0 = __half22float2(*(__half2*)&sr.x);
        float2 s1 = __half22float2(*(__half2*)&sr.y);
        float4 b = *(const float4*)(bias + q * 4);
        float4 o;
        o.x = acc.x * dv + s0.x * snv + b.x;
        o.y = acc.y * dv + s0.y * snv + b.y;
        o.z = acc.z * dv + s1.x * snv + b.z;
        o.w = acc.w * dv + s1.y * snv + b.w;
        *(float4*)&g_bufB[(size_t)c * 64 + q * 4] = o;
    }
}

// ---------------- BN3 + global_add_pool (batch is sorted: run-accumulate) ----------------
#define POOL_CHUNK 128
__global__ void k_pool(const int* __restrict__ batch) {
    int f = threadIdx.x;  // 64 threads: one per feature
    int start = blockIdx.x * POOL_CHUNK;
    int end = start + POOL_CHUNK;
    if (end > NN) end = NN;
    if (start >= NN) return;
    float sc = g_bnsc[2][f], sh = g_bnsh[2][f];
    int cur = batch[start];
    float acc = 0.f;
    for (int n = start; n < end; n++) {
        int b = batch[n];
        if (b != cur) {
            atomicAdd(&g_pooled[cur * 64 + f], acc);
            acc = 0.f;
            cur = b;
        }
        acc += g_bufB[(size_t)n * 64 + f] * sc + sh;
    }
    atomicAdd(&g_pooled[cur * 64 + f], acc);
}

// ---------------- FC: out[g] = relu(pooled[g]) . Wfc + bfc ----------------
__global__ void k_fc(const float* __restrict__ Wfc, const float* __restrict__ bfc,
                     float* __restrict__ out) {
    int g = threadIdx.x;  // 128
    float acc = 0.f;
#pragma unroll
    for (int k = 0; k < 64; k++)
        acc += fmaxf(g_pooled[g * 64 + k], 0.f) * Wfc[k];
    out[g] = acc + bfc[0];
}

// ---------------- launch ----------------
extern "C" void kernel_launch(void* const* d_in, const int* in_sizes, int n_in,
                              void* d_out, int out_size) {
    const float* x     = (const float*)d_in[0];
    const int*   ei    = (const int*)d_in[1];
    const int*   row   = ei;
    const int*   col   = ei + EE;
    const float* ew    = (const float*)d_in[2];
    const int*   batch = (const int*)d_in[3];
    const float* W1 = (const float*)d_in[4];
    const float* b1 = (const float*)d_in[5];
    const float* W2 = (const float*)d_in[6];
    const float* b2 = (const float*)d_in[7];
    const float* W3 = (const float*)d_in[8];
    const float* b3 = (const float*)d_in[9];
    const float* Wfc = (const float*)d_in[10];
    const float* bfc = (const float*)d_in[11];

    BNParams bp;
    for (int i = 0; i < 12; i++) bp.p[i] = (const float*)d_in[12 + i];

    int nb_n = (NN + 255) / 256;          // 391
    int nb_e = (EE + 255) / 256;          // 6250
    int nb_gemm = (NN + GR - 1) / GR;     // 782
    int nb_agg = NN / 8;                  // 12500
    int nb_pool = (NN + POOL_CHUNK - 1) / POOL_CHUNK; // 782

    // CSR build + norm precompute
    k_prep<<<nb_n, 256>>>(bp);
    k_degcount<<<nb_e, 256>>>(col, ew);
    k_scan1<<<SCAN_NBLK, SCAN_B>>>();
    k_scan2<<<1, 32>>>();
    k_fix<<<nb_n, 256>>>();
    k_scatter<<<nb_e, 256>>>(row, col, ew);

    // layer 1
    k_gemm1<<<nb_gemm, 128>>>(x, W1);
    k_agg<<<nb_agg, 256>>>(b1);
    // layer 2 (relu + bn1 fused into gemm input)
    k_gemm23<<<nb_gemm, 128>>>(W2, 0);
    k_agg<<<nb_agg, 256>>>(b2);
    // layer 3 (relu + bn2 fused into gemm input)
    k_gemm23<<<nb_gemm, 128>>>(W3, 1);
    k_agg<<<nb_agg, 256>>>(b3);

    // bn3 (no relu) + pool, then fc
    k_pool<<<nb_pool, 64>>>(batch);
    k_fc<<<1, 128>>>(Wfc, bfc, (float*)d_out);
}